// round 4
// baseline (speedup 1.0000x reference)
#include <cuda_runtime.h>

// ---------------------------------------------------------------------------
// enc_mtan_classif — collapsed computation:
//   A[b,c]  = masked mean of x over t (softmax broadcast quirk kills Q/K path)
//   G[b,n]  = A @ Wo^T + bo
//   gi[b,j] = G @ W_ih^T + b_ih       (GRU input identical at every step)
//   GRU 128 steps, 256 threads: each quad of lanes owns TWO hidden units
//   (6 gate-rows); lane q handles 32-dim quarter q of all 6 rows.
//   -> 8 LDS.128 feeding 96 fma2 per thread per step (12:1), 2-stage quad
//      shfl reduce, tail shared across units via lane-select, 1 barrier/step.
//   out = MLP(hT)
// ---------------------------------------------------------------------------

#define NTHR 256  // 8 warps x 8 quads x 2 units = 128 units

__device__ float  g_WihT[128 * 384];   // [n][j] = W_ih[j,n]
__device__ float2 g_Wq2[8 * 96 * 32];  // [w][r_idx*16+m][lane] W_hh pairs
__device__ float  g_W1T[128 * 300];    // [k][i] = W1[i,k]
__device__ float  g_W2T[300 * 300];    // [k][i] = W2[i,k]

__global__ void prep_kernel(const float* __restrict__ W_ih,
                            const float* __restrict__ W_hh,
                            const float* __restrict__ W1,
                            const float* __restrict__ W2) {
    int idx = blockIdx.x * blockDim.x + threadIdx.x;
    if (idx < 49152) {  // W_ih transpose
        int j = idx >> 7, k = idx & 127;
        g_WihT[k * 384 + j] = W_ih[idx];
        return;
    }
    int p = idx - 49152;
    if (p < 24576) {  // W_hh quad2-packed
        int w = p / 3072;
        int rem = p - w * 3072;
        int rm = rem >> 5;      // r_idx*16 + m
        int l = rem & 31;
        int r_idx = rm >> 4, m = rm & 15;
        int t = l >> 2, q = l & 3;
        int u = r_idx / 3, g = r_idx - 3 * u;
        int j = 2 * (8 * w + t) + u;
        int row = g * 128 + j;
        int col = 32 * q + 2 * m;
        g_Wq2[p] = make_float2(W_hh[row * 128 + col], W_hh[row * 128 + col + 1]);
        return;
    }
    p -= 24576;
    if (p < 38400) {  // W1 transpose
        int i = p >> 7, k = p & 127;
        g_W1T[k * 300 + i] = W1[p];
        return;
    }
    p -= 38400;
    if (p < 90000) {  // W2 transpose
        int i = p / 300, k = p - i * 300;
        g_W2T[k * 300 + i] = W2[p];
    }
}

typedef unsigned long long ull;

__device__ __forceinline__ void fma2(ull& d, ull a, ull b) {
    asm("fma.rn.f32x2 %0, %1, %2, %0;" : "+l"(d) : "l"(a), "l"(b));
}
__device__ __forceinline__ ull pack2(float lo, float hi) {
    ull r;
    asm("mov.b64 %0, {%1, %2};" : "=l"(r) : "f"(lo), "f"(hi));
    return r;
}
__device__ __forceinline__ float2 unpack2(ull v) {
    float2 f;
    asm("mov.b64 {%0, %1}, %2;" : "=f"(f.x), "=f"(f.y) : "l"(v));
    return f;
}
__device__ __forceinline__ float rcp_fast(float x) {
    float r;
    asm("rcp.approx.f32 %0, %1;" : "=f"(r) : "f"(x));
    return r;
}
__device__ __forceinline__ float sigmoid_f(float x) {
    return rcp_fast(1.0f + __expf(-x));
}
__device__ __forceinline__ float tanh_f(float x) {
    float r = rcp_fast(1.0f + __expf(-2.0f * x));
    return fmaf(2.0f, r, -1.0f);
}

__global__ __launch_bounds__(NTHR, 1) void mtan_kernel(
    const float* __restrict__ x,
    const float* __restrict__ Wo, const float* __restrict__ bo,
    const float* __restrict__ b_ih, const float* __restrict__ b_hh,
    const float* __restrict__ b1, const float* __restrict__ b2,
    const float* __restrict__ W3, const float* __restrict__ b3,
    float* __restrict__ out) {
    __shared__ __align__(16) float x_s[128 * 32];
    __shared__ float red[3][8][32];
    __shared__ float A_s[32];
    __shared__ __align__(16) float G_s[128];
    __shared__ __align__(16) float h_s[4 * 36];  // quarter-padded
    __shared__ float gi_s[384];
    __shared__ float y1_s[300];
    __shared__ float y2_s[300];

    const int tid = threadIdx.x;
    const int b = blockIdx.x;

    // ---- load x[b] (16KB) into smem, coalesced float4 ----
    {
        const float4* xg = reinterpret_cast<const float4*>(x + b * 4096);
        float4* xs4 = reinterpret_cast<float4*>(x_s);
        for (int i = tid; i < 1024; i += NTHR) xs4[i] = xg[i];
    }
    __syncthreads();

    // ---- masked mean A[c] over t ----
    {
        int c = tid & 31, seg = tid >> 5;  // 8 segments x 16 t's
        float num = 0.f, den = 0.f, tot = 0.f;
        for (int t = seg; t < 128; t += 8) {
            float v = x_s[t * 32 + c];
            float m = x_s[t * 32 + 16 + (c & 15)];
            num = fmaf(m, v, num);
            den += m;
            tot += v;
        }
        red[0][seg][c] = num;
        red[1][seg][c] = den;
        red[2][seg][c] = tot;
    }
    __syncthreads();
    if (tid < 32) {
        float n = 0.f, d = 0.f, t = 0.f;
#pragma unroll
        for (int s = 0; s < 8; ++s) {
            n += red[0][s][tid];
            d += red[1][s][tid];
            t += red[2][s][tid];
        }
        A_s[tid] = (d > 0.5f) ? (n / d) : (t * (1.0f / 128.0f));
    }
    __syncthreads();

    // ---- G[n] = A @ Wo^T + bo ----
    if (tid < 128) {
        float acc = bo[tid];
        const float* wrow = Wo + tid * 32;
#pragma unroll
        for (int c = 0; c < 32; ++c) acc = fmaf(A_s[c], wrow[c], acc);
        G_s[tid] = acc;
    }
    __syncthreads();

    // ---- gi[row] = G @ W_ih^T + b_ih -> smem (coalesced) ----
    for (int rr = tid; rr < 384; rr += NTHR) {
        float a0 = b_ih[rr], a1 = 0.f, a2 = 0.f, a3 = 0.f;
#pragma unroll 4
        for (int n = 0; n < 128; n += 4) {
            a0 = fmaf(G_s[n + 0], g_WihT[(n + 0) * 384 + rr], a0);
            a1 = fmaf(G_s[n + 1], g_WihT[(n + 1) * 384 + rr], a1);
            a2 = fmaf(G_s[n + 2], g_WihT[(n + 2) * 384 + rr], a2);
            a3 = fmaf(G_s[n + 3], g_WihT[(n + 3) * 384 + rr], a3);
        }
        gi_s[rr] = ((a0 + a1) + (a2 + a3));
    }
    if (tid < 144) h_s[tid] = 0.f;
    __syncthreads();

    // ---- GRU mapping: warp w, quad t -> units j0=2(8w+t), j0+1; lane q = quarter
    const int w = tid >> 5, l = tid & 31;
    const int t8 = l >> 2, q = l & 3;
    const int j0 = 2 * (8 * w + t8);
    const int jm = j0 + (q & 1);                 // unit this lane's tail serves
    const int qbase = q * 36;                    // my quarter in padded h_s
    const int hoff = (jm >> 5) * 36 + (jm & 31); // where unit jm's h lives

    const float e0 = gi_s[jm] + b_hh[jm];              // r
    const float e1 = gi_s[128 + jm] + b_hh[128 + jm];  // z
    const float e2 = b_hh[256 + jm];                   // hn dot bias
    const float gin = gi_s[256 + jm];                  // inn + b_in

    // ---- W_hh -> 96 packed regs (coalesced one-time load) ----
    ull wr[96];
    {
        const float2* wp = g_Wq2 + w * 3072 + l;
#pragma unroll
        for (int r = 0; r < 96; ++r) {
            float2 v = wp[r * 32];
            wr[r] = pack2(v.x, v.y);
        }
    }

    float hj = 0.f;
    __syncthreads();

    // ---- 128 GRU steps, one barrier per step ----
#pragma unroll 1
    for (int step = 0; step < 128; ++step) {
        ull A0 = 0ULL, A1 = 0ULL, A2 = 0ULL, A3 = 0ULL, A4 = 0ULL, A5 = 0ULL;
#pragma unroll
        for (int c = 0; c < 8; ++c) {
            float4 hv = *reinterpret_cast<const float4*>(h_s + qbase + 4 * c);
            ull hlo = pack2(hv.x, hv.y);
            ull hhi = pack2(hv.z, hv.w);
            fma2(A0, wr[0 * 16 + 2 * c], hlo);
            fma2(A1, wr[1 * 16 + 2 * c], hlo);
            fma2(A2, wr[2 * 16 + 2 * c], hlo);
            fma2(A3, wr[3 * 16 + 2 * c], hlo);
            fma2(A4, wr[4 * 16 + 2 * c], hlo);
            fma2(A5, wr[5 * 16 + 2 * c], hlo);
            fma2(A0, wr[0 * 16 + 2 * c + 1], hhi);
            fma2(A1, wr[1 * 16 + 2 * c + 1], hhi);
            fma2(A2, wr[2 * 16 + 2 * c + 1], hhi);
            fma2(A3, wr[3 * 16 + 2 * c + 1], hhi);
            fma2(A4, wr[4 * 16 + 2 * c + 1], hhi);
            fma2(A5, wr[5 * 16 + 2 * c + 1], hhi);
        }
        float2 f0 = unpack2(A0), f1 = unpack2(A1), f2 = unpack2(A2);
        float2 f3 = unpack2(A3), f4 = unpack2(A4), f5 = unpack2(A5);
        float d0 = f0.x + f0.y;  // unit j0: r
        float d1 = f1.x + f1.y;  //          z
        float d2 = f2.x + f2.y;  //          n
        float d3 = f3.x + f3.y;  // unit j0+1: r
        float d4 = f4.x + f4.y;  //            z
        float d5 = f5.x + f5.y;  //            n
        d0 += __shfl_xor_sync(0xffffffffu, d0, 1);
        d1 += __shfl_xor_sync(0xffffffffu, d1, 1);
        d2 += __shfl_xor_sync(0xffffffffu, d2, 1);
        d3 += __shfl_xor_sync(0xffffffffu, d3, 1);
        d4 += __shfl_xor_sync(0xffffffffu, d4, 1);
        d5 += __shfl_xor_sync(0xffffffffu, d5, 1);
        d0 += __shfl_xor_sync(0xffffffffu, d0, 2);
        d1 += __shfl_xor_sync(0xffffffffu, d1, 2);
        d2 += __shfl_xor_sync(0xffffffffu, d2, 2);
        d3 += __shfl_xor_sync(0xffffffffu, d3, 2);
        d4 += __shfl_xor_sync(0xffffffffu, d4, 2);
        d5 += __shfl_xor_sync(0xffffffffu, d5, 2);
        // lane-select: odd lanes serve unit j0+1, even serve j0
        bool odd = (q & 1);
        float dr = odd ? d3 : d0;
        float dz = odd ? d4 : d1;
        float dn = odd ? d5 : d2;
        float r = sigmoid_f(dr + e0);
        float z = sigmoid_f(dz + e1);
        float n = tanh_f(fmaf(r, dn + e2, gin));
        hj = n + z * (hj - n);
        if (q < 2) h_s[hoff] = hj;
        __syncthreads();
    }

    // gather final h contiguously into gi_s scratch
    if ((q & 2) == 0) gi_s[jm] = hj;  // lanes 0,1 of each quad
    __syncthreads();
    const float* hfin = gi_s;

    // ---- MLP head: 128 -> 300 -> 300 -> 2 ----
    for (int i = tid; i < 300; i += NTHR) {
        float a0 = b1[i], a1 = 0.f, a2 = 0.f, a3 = 0.f;
#pragma unroll 4
        for (int k = 0; k < 128; k += 4) {
            a0 = fmaf(hfin[k + 0], g_W1T[(k + 0) * 300 + i], a0);
            a1 = fmaf(hfin[k + 1], g_W1T[(k + 1) * 300 + i], a1);
            a2 = fmaf(hfin[k + 2], g_W1T[(k + 2) * 300 + i], a2);
            a3 = fmaf(hfin[k + 3], g_W1T[(k + 3) * 300 + i], a3);
        }
        y1_s[i] = fmaxf((a0 + a1) + (a2 + a3), 0.f);
    }
    __syncthreads();
    for (int i = tid; i < 300; i += NTHR) {
        float a0 = b2[i], a1 = 0.f, a2 = 0.f, a3 = 0.f;
#pragma unroll 4
        for (int k = 0; k < 300; k += 4) {
            a0 = fmaf(y1_s[k + 0], g_W2T[(k + 0) * 300 + i], a0);
            a1 = fmaf(y1_s[k + 1], g_W2T[(k + 1) * 300 + i], a1);
            a2 = fmaf(y1_s[k + 2], g_W2T[(k + 2) * 300 + i], a2);
            a3 = fmaf(y1_s[k + 3], g_W2T[(k + 3) * 300 + i], a3);
        }
        y2_s[i] = fmaxf((a0 + a1) + (a2 + a3), 0.f);
    }
    __syncthreads();
    {
        int wo = tid >> 5, lo = tid & 31;
        if (wo < 2) {
            float a = 0.f;
            for (int k = lo; k < 300; k += 32)
                a = fmaf(y2_s[k], W3[wo * 300 + k], a);
#pragma unroll
            for (int off = 16; off; off >>= 1)
                a += __shfl_down_sync(0xffffffffu, a, off);
            if (lo == 0) out[b * 2 + wo] = a + b3[wo];
        }
    }
}

extern "C" void kernel_launch(void* const* d_in, const int* in_sizes, int n_in,
                              void* d_out, int out_size) {
    (void)in_sizes;
    (void)n_in;
    (void)out_size;
    const float* x = (const float*)d_in[0];
    // d_in[1..9] (query_p, time-embedding + Q/K proj weights) are provably
    // dead: the broadcast quirk makes softmax uniform over valid mask slots.
    const float* Wo = (const float*)d_in[10];
    const float* bo = (const float*)d_in[11];
    const float* W_ih = (const float*)d_in[12];
    const float* W_hh = (const float*)d_in[13];
    const float* b_ih = (const float*)d_in[14];
    const float* b_hh = (const float*)d_in[15];
    const float* W1 = (const float*)d_in[16];
    const float* b1 = (const float*)d_in[17];
    const float* W2 = (const float*)d_in[18];
    const float* b2 = (const float*)d_in[19];
    const float* W3 = (const float*)d_in[20];
    const float* b3 = (const float*)d_in[21];
    float* out = (float*)d_out;

    const int total = 49152 + 24576 + 38400 + 90000;
    prep_kernel<<<(total + 255) / 256, 256>>>(W_ih, W_hh, W1, W2);
    mtan_kernel<<<128, NTHR>>>(x, Wo, bo, b_ih, b_hh, b1, b2, W3, b3, out);
}

// round 5
// speedup vs baseline: 1.2298x; 1.2298x over previous
#include <cuda_runtime.h>

// ---------------------------------------------------------------------------
// enc_mtan_classif — collapsed computation:
//   A[b,c]  = masked mean of x over t (softmax broadcast quirk kills Q/K path)
//   G[b,n]  = A @ Wo^T + bo
//   gi[b,j] = G @ W_ih^T + b_ih       (GRU input identical at every step)
//   GRU 128 steps: quad-of-lanes per hidden unit (R3 mapping), tail rebuilt:
//     - MUFU.TANH for both sigmoids (one lane-split instr) and tanh
//     - 4-shfl transposed reduce for r/z + 2-shfl for n, 2 broadcast shfl
//     - ONE barrier per step
//   out = MLP(hT)
// ---------------------------------------------------------------------------

#define NTHR 512  // 16 warps x 8 units = 128 units

__device__ float  g_WihT[128 * 384];      // [n][j] = W_ih[j,n]
__device__ float2 g_Wq[16 * 3 * 16 * 32]; // [w][g][m][l] packed W_hh pairs
__device__ float  g_W1T[128 * 300];       // [k][i] = W1[i,k]
__device__ float  g_W2T[300 * 300];       // [k][i] = W2[i,k]

__global__ void prep_kernel(const float* __restrict__ W_ih,
                            const float* __restrict__ W_hh,
                            const float* __restrict__ W1,
                            const float* __restrict__ W2) {
    int idx = blockIdx.x * blockDim.x + threadIdx.x;
    if (idx < 49152) {  // W_ih transpose
        int j = idx >> 7, k = idx & 127;
        g_WihT[k * 384 + j] = W_ih[idx];
        return;
    }
    int p = idx - 49152;
    if (p < 24576) {  // W_hh quad-packed
        int w = p / 1536;
        int r1 = p - w * 1536;
        int g = r1 >> 9;
        int r2 = r1 & 511;
        int m = r2 >> 5, l = r2 & 31;
        int j = w * 8 + (l >> 2);
        int q = l & 3;
        int row = g * 128 + j;
        int col = q * 32 + 2 * m;
        g_Wq[p] = make_float2(W_hh[row * 128 + col], W_hh[row * 128 + col + 1]);
        return;
    }
    p -= 24576;
    if (p < 38400) {  // W1 transpose
        int i = p >> 7, k = p & 127;
        g_W1T[k * 300 + i] = W1[p];
        return;
    }
    p -= 38400;
    if (p < 90000) {  // W2 transpose
        int i = p / 300, k = p - i * 300;
        g_W2T[k * 300 + i] = W2[p];
    }
}

typedef unsigned long long ull;

__device__ __forceinline__ void fma2(ull& d, ull a, ull b) {
    asm("fma.rn.f32x2 %0, %1, %2, %0;" : "+l"(d) : "l"(a), "l"(b));
}
__device__ __forceinline__ ull pack2(float lo, float hi) {
    ull r;
    asm("mov.b64 %0, {%1, %2};" : "=l"(r) : "f"(lo), "f"(hi));
    return r;
}
__device__ __forceinline__ float2 unpack2(ull v) {
    float2 f;
    asm("mov.b64 {%0, %1}, %2;" : "=f"(f.x), "=f"(f.y) : "l"(v));
    return f;
}
__device__ __forceinline__ float tanhx(float x) {
    float r;
    asm("tanh.approx.f32 %0, %1;" : "=f"(r) : "f"(x));
    return r;
}

__global__ __launch_bounds__(NTHR, 1) void mtan_kernel(
    const float* __restrict__ x,
    const float* __restrict__ Wo, const float* __restrict__ bo,
    const float* __restrict__ b_ih, const float* __restrict__ b_hh,
    const float* __restrict__ b1, const float* __restrict__ b2,
    const float* __restrict__ W3, const float* __restrict__ b3,
    float* __restrict__ out) {
    __shared__ __align__(16) float x_s[128 * 32];
    __shared__ float red[3][16][32];
    __shared__ float A_s[32];
    __shared__ __align__(16) float G_s[128];
    __shared__ __align__(16) float h_s[4 * 36];  // quarter-padded
    __shared__ float gi_s[384];
    __shared__ float y1_s[300];
    __shared__ float y2_s[300];

    const int tid = threadIdx.x;
    const int b = blockIdx.x;

    // ---- load x[b] (16KB) into smem, coalesced float4 ----
    {
        const float4* xg = reinterpret_cast<const float4*>(x + b * 4096);
        float4* xs4 = reinterpret_cast<float4*>(x_s);
        for (int i = tid; i < 1024; i += NTHR) xs4[i] = xg[i];
    }
    __syncthreads();

    // ---- masked mean A[c] over t ----
    {
        int c = tid & 31, seg = tid >> 5;
        float num = 0.f, den = 0.f, tot = 0.f;
        for (int t = seg; t < 128; t += 16) {
            float v = x_s[t * 32 + c];
            float m = x_s[t * 32 + 16 + (c & 15)];
            num = fmaf(m, v, num);
            den += m;
            tot += v;
        }
        red[0][seg][c] = num;
        red[1][seg][c] = den;
        red[2][seg][c] = tot;
    }
    __syncthreads();
    if (tid < 32) {
        float n = 0.f, d = 0.f, t = 0.f;
#pragma unroll
        for (int s = 0; s < 16; ++s) {
            n += red[0][s][tid];
            d += red[1][s][tid];
            t += red[2][s][tid];
        }
        A_s[tid] = (d > 0.5f) ? (n / d) : (t * (1.0f / 128.0f));
    }
    __syncthreads();

    // ---- G[n] = A @ Wo^T + bo ----
    if (tid < 128) {
        float acc = bo[tid];
        const float* wrow = Wo + tid * 32;
#pragma unroll
        for (int c = 0; c < 32; ++c) acc = fmaf(A_s[c], wrow[c], acc);
        G_s[tid] = acc;
    }
    __syncthreads();

    // ---- gi[row] = G @ W_ih^T + b_ih -> smem (coalesced) ----
    if (tid < 384) {
        float a0 = b_ih[tid], a1 = 0.f, a2 = 0.f, a3 = 0.f;
#pragma unroll 4
        for (int n = 0; n < 128; n += 4) {
            a0 = fmaf(G_s[n + 0], g_WihT[(n + 0) * 384 + tid], a0);
            a1 = fmaf(G_s[n + 1], g_WihT[(n + 1) * 384 + tid], a1);
            a2 = fmaf(G_s[n + 2], g_WihT[(n + 2) * 384 + tid], a2);
            a3 = fmaf(G_s[n + 3], g_WihT[(n + 3) * 384 + tid], a3);
        }
        gi_s[tid] = ((a0 + a1) + (a2 + a3));
    }
    if (tid < 144) h_s[tid] = 0.f;
    __syncthreads();

    // ---- GRU mapping: warp w, quad (l>>2) -> unit j; lane q = l&3 -> quarter
    const int w = tid >> 5, l = tid & 31;
    const int j = w * 8 + (l >> 2);
    const int q = l & 3;
    const int qbase = q * 36;
    const int hoff = (j >> 5) * 36 + (j & 31);
    const int base = l & ~3;  // lane of q==0 in this quad
    const bool leader = (q == 0);
    const bool oddlane = (q & 1);

    // even lanes (0,2) -> r gate, odd lanes (1,3) -> z gate for the one MUFU
    const float eh = 0.5f * (oddlane ? (gi_s[128 + j] + b_hh[128 + j])
                                     : (gi_s[j] + b_hh[j]));
    const float e2 = b_hh[256 + j];   // hn dot bias
    const float gin = gi_s[256 + j];  // inn + b_in

    // ---- W_hh -> 48 packed regs (coalesced one-time load) ----
    ull wr[48];
    {
        const float2* wp = g_Wq + (w * 3) * 512 + l;
#pragma unroll
        for (int g = 0; g < 3; ++g)
#pragma unroll
            for (int m = 0; m < 16; ++m) {
                float2 t = wp[g * 512 + m * 32];
                wr[g * 16 + m] = pack2(t.x, t.y);
            }
    }

    float hj = 0.f;
    __syncthreads();

    const ulonglong2* hs2 = reinterpret_cast<const ulonglong2*>(h_s);

    // ---- 128 GRU steps, one barrier per step ----
#pragma unroll 1
    for (int step = 0; step < 128; ++step) {
        ull a0 = 0ULL, a1 = 0ULL, a2 = 0ULL;
#pragma unroll
        for (int i = 0; i < 8; i += 2) {
            ulonglong2 h0 = hs2[(qbase >> 2) + i];
            ulonglong2 h1 = hs2[(qbase >> 2) + i + 1];
            fma2(a0, wr[2 * i + 0], h0.x);
            fma2(a1, wr[16 + 2 * i + 0], h0.x);
            fma2(a2, wr[32 + 2 * i + 0], h0.x);
            fma2(a0, wr[2 * i + 1], h0.y);
            fma2(a1, wr[16 + 2 * i + 1], h0.y);
            fma2(a2, wr[32 + 2 * i + 1], h0.y);
            fma2(a0, wr[2 * i + 2], h1.x);
            fma2(a1, wr[16 + 2 * i + 2], h1.x);
            fma2(a2, wr[32 + 2 * i + 2], h1.x);
            fma2(a0, wr[2 * i + 3], h1.y);
            fma2(a1, wr[16 + 2 * i + 3], h1.y);
            fma2(a2, wr[32 + 2 * i + 3], h1.y);
        }
        float2 f0 = unpack2(a0), f1 = unpack2(a1), f2 = unpack2(a2);
        float d0 = f0.x + f0.y;  // r partial (this lane's quarter)
        float d1 = f1.x + f1.y;  // z partial
        float d2 = f2.x + f2.y;  // n partial
        // transposed reduce: r/z share one butterfly; even lanes end with
        // full r-dot, odd lanes with full z-dot
        float own = oddlane ? d1 : d0;
        float snd = oddlane ? d0 : d1;
        float u = own + __shfl_xor_sync(0xffffffffu, snd, 1);
        float Dsel = u + __shfl_xor_sync(0xffffffffu, u, 2);
        float t2 = d2 + __shfl_xor_sync(0xffffffffu, d2, 1);
        float D2 = t2 + __shfl_xor_sync(0xffffffffu, t2, 2);
        // ONE MUFU computes sigma(r) on even lanes and sigma(z) on odd lanes
        float v = fmaf(0.5f, tanhx(fmaf(0.5f, Dsel, eh)), 0.5f);
        float r = __shfl_sync(0xffffffffu, v, base);      // from lane q==0
        float z = __shfl_sync(0xffffffffu, v, base + 1);  // from lane q==1
        float n = tanhx(fmaf(r, D2 + e2, gin));
        hj = n + z * (hj - n);
        if (leader) h_s[hoff] = hj;
        __syncthreads();
    }

    // gather final h contiguously into gi_s scratch
    if (leader) gi_s[j] = hj;
    __syncthreads();
    const float* hfin = gi_s;

    // ---- MLP head: 128 -> 300 -> 300 -> 2 ----
    if (tid < 300) {
        float a0 = b1[tid], a1 = 0.f, a2 = 0.f, a3 = 0.f;
#pragma unroll 4
        for (int k = 0; k < 128; k += 4) {
            a0 = fmaf(hfin[k + 0], g_W1T[(k + 0) * 300 + tid], a0);
            a1 = fmaf(hfin[k + 1], g_W1T[(k + 1) * 300 + tid], a1);
            a2 = fmaf(hfin[k + 2], g_W1T[(k + 2) * 300 + tid], a2);
            a3 = fmaf(hfin[k + 3], g_W1T[(k + 3) * 300 + tid], a3);
        }
        y1_s[tid] = fmaxf((a0 + a1) + (a2 + a3), 0.f);
    }
    __syncthreads();
    if (tid < 300) {
        float a0 = b2[tid], a1 = 0.f, a2 = 0.f, a3 = 0.f;
#pragma unroll 4
        for (int k = 0; k < 300; k += 4) {
            a0 = fmaf(y1_s[k + 0], g_W2T[(k + 0) * 300 + tid], a0);
            a1 = fmaf(y1_s[k + 1], g_W2T[(k + 1) * 300 + tid], a1);
            a2 = fmaf(y1_s[k + 2], g_W2T[(k + 2) * 300 + tid], a2);
            a3 = fmaf(y1_s[k + 3], g_W2T[(k + 3) * 300 + tid], a3);
        }
        y2_s[tid] = fmaxf((a0 + a1) + (a2 + a3), 0.f);
    }
    __syncthreads();
    {
        int wo = tid >> 5, lo = tid & 31;
        if (wo < 2) {
            float a = 0.f;
            for (int k = lo; k < 300; k += 32)
                a = fmaf(y2_s[k], W3[wo * 300 + k], a);
#pragma unroll
            for (int off = 16; off; off >>= 1)
                a += __shfl_down_sync(0xffffffffu, a, off);
            if (lo == 0) out[b * 2 + wo] = a + b3[wo];
        }
    }
}

extern "C" void kernel_launch(void* const* d_in, const int* in_sizes, int n_in,
                              void* d_out, int out_size) {
    (void)in_sizes;
    (void)n_in;
    (void)out_size;
    const float* x = (const float*)d_in[0];
    // d_in[1..9] (query_p, time-embedding + Q/K proj weights) are provably
    // dead: the broadcast quirk makes softmax uniform over valid mask slots.
    const float* Wo = (const float*)d_in[10];
    const float* bo = (const float*)d_in[11];
    const float* W_ih = (const float*)d_in[12];
    const float* W_hh = (const float*)d_in[13];
    const float* b_ih = (const float*)d_in[14];
    const float* b_hh = (const float*)d_in[15];
    const float* W1 = (const float*)d_in[16];
    const float* b1 = (const float*)d_in[17];
    const float* W2 = (const float*)d_in[18];
    const float* b2 = (const float*)d_in[19];
    const float* W3 = (const float*)d_in[20];
    const float* b3 = (const float*)d_in[21];
    float* out = (float*)d_out;

    const int total = 49152 + 24576 + 38400 + 90000;
    prep_kernel<<<(total + 255) / 256, 256>>>(W_ih, W_hh, W1, W2);
    mtan_kernel<<<128, NTHR>>>(x, Wo, bo, b_ih, b_hh, b1, b2, W3, b3, out);
}